// round 3
// baseline (speedup 1.0000x reference)
#include <cuda_runtime.h>
#include <cstdint>

#define NQ   12
#define DIM  4096          // 2^12
#define NPAIR (DIM/2)
#define BATCH_THREADS 256

// Precomputed gate parameters (written by prep kernel each launch).
// d_U[layer][wire][0..3] = fused RZ*RY*RX 2x2 complex matrix (row-major u00,u01,u10,u11)
__device__ float2 d_U[2][NQ][4];
__device__ float  d_crx_c[2][NQ];   // cos(theta/2) for CRX with control wire i
__device__ float  d_crx_s[2][NQ];   // sin(theta/2)

__device__ __forceinline__ float2 cmul(float2 a, float2 b) {
    return make_float2(a.x * b.x - a.y * b.y, a.x * b.y + a.y * b.x);
}
__device__ __forceinline__ float2 cadd(float2 a, float2 b) {
    return make_float2(a.x + b.x, a.y + b.y);
}

// ---------------------------------------------------------------------------
// Prep kernel: fold the 3 single-qubit rotations per wire per layer into one
// 2x2 unitary; extract CRX cos/sin. 24 threads do all the work.
// ---------------------------------------------------------------------------
__global__ void prep_gates(const float* __restrict__ angles) {
    int t = threadIdx.x;
    if (t >= 24) return;
    int l = t / NQ;
    int i = t % NQ;          // wire index
    int base = l * 48;
    float ax = angles[base + i];
    float ay = angles[base + NQ + i];
    float az = angles[base + 2 * NQ + i];

    float cx = cosf(0.5f * ax), sx = sinf(0.5f * ax);
    float cy = cosf(0.5f * ay), sy = sinf(0.5f * ay);
    float cz = cosf(0.5f * az), sz = sinf(0.5f * az);

    // M = RY * RX
    float2 m00 = make_float2(cy * cx,  sy * sx);
    float2 m01 = make_float2(-sy * cx, -cy * sx);
    float2 m10 = make_float2(sy * cx,  -cy * sx);
    float2 m11 = make_float2(cy * cx,  -sy * sx);
    // U = RZ * M : row0 *= e^{-i az/2}, row1 *= e^{+i az/2}
    float2 em = make_float2(cz, -sz);
    float2 ep = make_float2(cz,  sz);
    d_U[l][i][0] = cmul(em, m00);
    d_U[l][i][1] = cmul(em, m01);
    d_U[l][i][2] = cmul(ep, m10);
    d_U[l][i][3] = cmul(ep, m11);

    // CRX with control wire i: layer0 -> g = 36 + i ; layer1 -> g = 84 + (11 - i)
    int g = (l == 0) ? (36 + i) : (84 + (NQ - 1 - i));
    float th = angles[g];
    d_crx_c[l][i] = cosf(0.5f * th);
    d_crx_s[l][i] = sinf(0.5f * th);
}

// ---------------------------------------------------------------------------
// Main kernel: one CTA per batch state. State lives in shared memory.
// Wire w of the reference maps to bit (11 - w) of the flat amplitude index.
// ---------------------------------------------------------------------------
__global__ __launch_bounds__(BATCH_THREADS)
void sim_kernel(const float* __restrict__ sv,
                const float* __restrict__ W,
                const float* __restrict__ bvec,
                float* __restrict__ out) {
    __shared__ float2 s[DIM];            // 32 KB state
    __shared__ float  s_red[36 * 8];     // per-warp partial features
    __shared__ float  s_feat[36];
    // local copy of gate params (broadcast-loaded once)
    __shared__ float2 su[2][NQ][4];
    __shared__ float  scc[2][NQ], scs[2][NQ];

    const int tid  = threadIdx.x;
    const int bidx = blockIdx.x;

    // load gate params into smem
    if (tid < 24) {
        int l = tid / NQ, i = tid % NQ;
        su[l][i][0] = d_U[l][i][0];
        su[l][i][1] = d_U[l][i][1];
        su[l][i][2] = d_U[l][i][2];
        su[l][i][3] = d_U[l][i][3];
        scc[l][i] = d_crx_c[l][i];
        scs[l][i] = d_crx_s[l][i];
    }

    // load state (real input -> complex)
    const float4* in4 = (const float4*)(sv + (size_t)bidx * DIM);
    #pragma unroll
    for (int k = tid; k < DIM / 4; k += BATCH_THREADS) {
        float4 v = in4[k];
        s[4 * k + 0] = make_float2(v.x, 0.f);
        s[4 * k + 1] = make_float2(v.y, 0.f);
        s[4 * k + 2] = make_float2(v.z, 0.f);
        s[4 * k + 3] = make_float2(v.w, 0.f);
    }
    __syncthreads();

    for (int l = 0; l < 2; l++) {
        // ---- 12 fused single-qubit gates ----
        for (int w = 0; w < NQ; w++) {
            const int q = 11 - w;                 // bit position
            const float2 u00 = su[l][w][0], u01 = su[l][w][1];
            const float2 u10 = su[l][w][2], u11 = su[l][w][3];
            const int mlow = (1 << q) - 1;
            for (int p = tid; p < NPAIR; p += BATCH_THREADS) {
                int i0 = ((p >> q) << (q + 1)) | (p & mlow);
                int i1 = i0 | (1 << q);
                float2 a = s[i0];
                float2 c = s[i1];
                s[i0] = cadd(cmul(u00, a), cmul(u01, c));
                s[i1] = cadd(cmul(u10, a), cmul(u11, c));
            }
            __syncthreads();
        }
        // ---- CRX ring (order matters) ----
        for (int k = 0; k < NQ; k++) {
            const int cw = (l == 0) ? k : (NQ - 1 - k);   // control wire
            const int tw = (cw + 1) % NQ;                 // target wire
            const int cb = 11 - cw;                       // control bit
            const int tb = 11 - tw;                       // target bit
            const float cc = scc[l][cw];
            const float ss = scs[l][cw];
            const int q1 = cb < tb ? cb : tb;
            const int q2 = cb < tb ? tb : cb;
            const int m1 = (1 << q1) - 1;
            const int m2 = (1 << q2) - 1;
            for (int p = tid; p < DIM / 4; p += BATCH_THREADS) {
                int i = ((p >> q1) << (q1 + 1)) | (p & m1);
                i = ((i >> q2) << (q2 + 1)) | (i & m2);
                int i0 = i | (1 << cb);          // control=1, target=0
                int i1 = i0 | (1 << tb);         // control=1, target=1
                float2 a = s[i0];
                float2 d = s[i1];
                // new0 = cc*a - i*ss*d ; new1 = -i*ss*a + cc*d
                s[i0] = make_float2(cc * a.x + ss * d.y, cc * a.y - ss * d.x);
                s[i1] = make_float2(cc * d.x + ss * a.y, cc * d.y - ss * a.x);
            }
            __syncthreads();
        }
    }

    // ---- expectation values <X_w>, <Y_w>, <Z_w> ----
    const int warp = tid >> 5, lane = tid & 31;
    for (int w = 0; w < NQ; w++) {
        const int q = 11 - w;
        const int mlow = (1 << q) - 1;
        float xr = 0.f, yi = 0.f, zz = 0.f;
        for (int p = tid; p < NPAIR; p += BATCH_THREADS) {
            int i0 = ((p >> q) << (q + 1)) | (p & mlow);
            int i1 = i0 | (1 << q);
            float2 a = s[i0];
            float2 c = s[i1];
            zz += (a.x * a.x + a.y * a.y) - (c.x * c.x + c.y * c.y);
            xr += a.x * c.x + a.y * c.y;     // Re(conj(a)*c)
            yi += a.x * c.y - a.y * c.x;     // Im(conj(a)*c)
        }
        #pragma unroll
        for (int o = 16; o; o >>= 1) {
            xr += __shfl_down_sync(0xffffffffu, xr, o);
            yi += __shfl_down_sync(0xffffffffu, yi, o);
            zz += __shfl_down_sync(0xffffffffu, zz, o);
        }
        if (lane == 0) {
            s_red[w * 8 + warp]        = 2.f * xr;  // X_w
            s_red[(12 + w) * 8 + warp] = 2.f * yi;  // Y_w
            s_red[(24 + w) * 8 + warp] = zz;        // Z_w
        }
    }
    __syncthreads();
    if (tid < 36) {
        float f = 0.f;
        #pragma unroll
        for (int r = 0; r < 8; r++) f += s_red[tid * 8 + r];
        s_feat[tid] = f;
    }
    __syncthreads();
    // ---- linear head: out = feats @ W.T + b ----
    if (tid < 10) {
        float acc = bvec[tid];
        #pragma unroll
        for (int j = 0; j < 36; j++) acc += W[tid * 36 + j] * s_feat[j];
        out[(size_t)bidx * 10 + tid] = acc;
    }
}

extern "C" void kernel_launch(void* const* d_in, const int* in_sizes, int n_in,
                              void* d_out, int out_size) {
    const float* sv     = (const float*)d_in[0];   // [2048, 4096]
    const float* angles = (const float*)d_in[1];   // [96]
    const float* W      = (const float*)d_in[2];   // [10, 36]
    const float* b      = (const float*)d_in[3];   // [10]
    float* out = (float*)d_out;                    // [2048, 10]

    prep_gates<<<1, 32>>>(angles);
    sim_kernel<<<2048, BATCH_THREADS>>>(sv, W, b, out);
}

// round 6
// speedup vs baseline: 2.2869x; 2.2869x over previous
#include <cuda_runtime.h>
#include <cstdint>

#define NQ   12
#define DIM  4096
#define NT   256

// Precomputed gate parameters (written by prep kernel each launch).
__device__ float2 d_U[2][NQ][4];     // fused RZ*RY*RX per layer per wire
__device__ float  d_crx[2][NQ][2];   // cos(th/2), sin(th/2), indexed by control WIRE

__device__ __forceinline__ float2 cmul(float2 a, float2 b) {
    return make_float2(a.x * b.x - a.y * b.y, a.x * b.y + a.y * b.x);
}

// ---------------------------------------------------------------------------
__global__ void prep_gates(const float* __restrict__ angles) {
    int t = threadIdx.x;
    if (t >= 24) return;
    int l = t / NQ;
    int i = t % NQ;
    int base = l * 48;
    float ax = angles[base + i];
    float ay = angles[base + NQ + i];
    float az = angles[base + 2 * NQ + i];

    float cx = cosf(0.5f * ax), sx = sinf(0.5f * ax);
    float cy = cosf(0.5f * ay), sy = sinf(0.5f * ay);
    float cz = cosf(0.5f * az), sz = sinf(0.5f * az);

    float2 m00 = make_float2(cy * cx,  sy * sx);
    float2 m01 = make_float2(-sy * cx, -cy * sx);
    float2 m10 = make_float2(sy * cx,  -cy * sx);
    float2 m11 = make_float2(cy * cx,  -sy * sx);
    float2 em = make_float2(cz, -sz);
    float2 ep = make_float2(cz,  sz);
    d_U[l][i][0] = cmul(em, m00);
    d_U[l][i][1] = cmul(em, m01);
    d_U[l][i][2] = cmul(ep, m10);
    d_U[l][i][3] = cmul(ep, m11);

    int g = (l == 0) ? (36 + i) : (84 + (NQ - 1 - i));
    float th = angles[g];
    d_crx[l][i][0] = cosf(0.5f * th);
    d_crx[l][i][1] = sinf(0.5f * th);
}

// ---------------------------------------------------------------------------
// Layout configs. Address bit b <-> wire (11-b).
//  cfg 0 (A): local bits {8,9,10,11}  lane {0..4}      warp {5,6,7}
//  cfg 1 (B): local bits {5,6,7,8}    lane {0..4}      warp {9,10,11}
//  cfg 2 (C): local bits {2,3,4,5}    lane {0,1,6,7,8} warp {9,10,11}
//  cfg 3 (D): local bits {0,1,2,11}   lane {3..7}      warp {8,9,10}
//  cfg 4 (E): local bits {4,5,6,7}    lane {0,1,2,3,8} warp {9,10,11}
//  cfg 5 (F): local bits {0,1,2,3}    lane {4..8}      warp {9,10,11}
// Padded smem addressing p = a + (a>>4) makes every config's strided
// read/write pattern bank-conflict-free (low nibble covers 16 values/half-warp).

__device__ __forceinline__ int padidx(int a) { return a + (a >> 4); }

template<int CFG>
__device__ __forceinline__ int baseof(int lane, int warp) {
    if (CFG == 0) return lane | (warp << 5);
    if (CFG == 1) return lane | (warp << 9);
    if (CFG == 2) return (lane & 3) | ((lane >> 2) << 6) | (warp << 9);
    if (CFG == 3) return (lane << 3) | (warp << 8);
    if (CFG == 4) return (lane & 15) | ((lane >> 4) << 8) | (warp << 9);
    return (lane << 4) | (warp << 9);
}
template<int CFG>
__device__ __forceinline__ int placeof(int j) {
    if (CFG == 0) return j << 8;
    if (CFG == 1) return j << 5;
    if (CFG == 2) return j << 2;
    if (CFG == 3) return (j & 7) | ((j >> 3) << 11);
    if (CFG == 4) return j << 4;
    return j;
}

template<int CX, int CY>
__device__ __forceinline__ void remap(float2* v, float2* s, int lane, int warp) {
    const int bx = baseof<CX>(lane, warp);
    #pragma unroll
    for (int j = 0; j < 16; j++) s[padidx(bx | placeof<CX>(j))] = v[j];
    __syncthreads();
    const int by = baseof<CY>(lane, warp);
    #pragma unroll
    for (int j = 0; j < 16; j++) v[j] = s[padidx(by | placeof<CY>(j))];
    __syncthreads();
}

// fused 1q gate on local bit K (register-only)
template<int K>
__device__ __forceinline__ void gate1q(float2* v, const float2* u) {
    const float2 u00 = u[0], u01 = u[1], u10 = u[2], u11 = u[3];
    #pragma unroll
    for (int m = 0; m < 8; m++) {
        int j0 = ((m >> K) << (K + 1)) | (m & ((1 << K) - 1));
        int j1 = j0 | (1 << K);
        float2 a = v[j0], b = v[j1];
        v[j0] = make_float2(u00.x * a.x - u00.y * a.y + u01.x * b.x - u01.y * b.y,
                            u00.x * a.y + u00.y * a.x + u01.x * b.y + u01.y * b.x);
        v[j1] = make_float2(u10.x * a.x - u10.y * a.y + u11.x * b.x - u11.y * b.y,
                            u10.x * a.y + u10.y * a.x + u11.x * b.y + u11.y * b.x);
    }
}

// CRX: control local bit CK, target local bit TK (register-only)
template<int CK, int TK>
__device__ __forceinline__ void gatecrx(float2* v, const float* p) {
    const float cc = p[0], ss = p[1];
    #pragma unroll
    for (int j = 0; j < 16; j++) {
        if (((j >> CK) & 1) == 1 && ((j >> TK) & 1) == 0) {
            int j1 = j | (1 << TK);
            float2 a = v[j];
            float2 d = v[j1];
            v[j]  = make_float2(cc * a.x + ss * d.y, cc * a.y - ss * d.x);
            v[j1] = make_float2(cc * d.x + ss * a.y, cc * d.y - ss * a.x);
        }
    }
}

// expectation values for local bit K -> feature wire W
template<int K>
__device__ __forceinline__ void expv(const float2* v, int wireW,
                                     int lane, int warp, float* s_red) {
    float xr = 0.f, yi = 0.f, zz = 0.f;
    #pragma unroll
    for (int m = 0; m < 8; m++) {
        int j0 = ((m >> K) << (K + 1)) | (m & ((1 << K) - 1));
        int j1 = j0 | (1 << K);
        float2 a = v[j0], c = v[j1];
        zz += (a.x * a.x + a.y * a.y) - (c.x * c.x + c.y * c.y);
        xr += a.x * c.x + a.y * c.y;
        yi += a.x * c.y - a.y * c.x;
    }
    #pragma unroll
    for (int o = 16; o; o >>= 1) {
        xr += __shfl_down_sync(0xffffffffu, xr, o);
        yi += __shfl_down_sync(0xffffffffu, yi, o);
        zz += __shfl_down_sync(0xffffffffu, zz, o);
    }
    if (lane == 0) {
        s_red[wireW * 8 + warp]        = 2.f * xr;
        s_red[(12 + wireW) * 8 + warp] = 2.f * yi;
        s_red[(24 + wireW) * 8 + warp] = zz;
    }
}

// ---------------------------------------------------------------------------
__global__ __launch_bounds__(NT)
void sim_kernel(const float* __restrict__ sv,
                const float* __restrict__ W,
                const float* __restrict__ bvec,
                float* __restrict__ out) {
    __shared__ float2 s[4352];           // padded state: 4096 + 256
    __shared__ float  s_red[36 * 8];
    __shared__ float  s_feat[36];
    __shared__ float2 su[2][NQ][4];
    __shared__ float  sc[2][NQ][2];

    const int tid  = threadIdx.x;
    const int lane = tid & 31;
    const int warp = tid >> 5;
    const int bidx = blockIdx.x;

    if (tid < 24) {
        int l = tid / NQ, i = tid % NQ;
        su[l][i][0] = d_U[l][i][0];
        su[l][i][1] = d_U[l][i][1];
        su[l][i][2] = d_U[l][i][2];
        su[l][i][3] = d_U[l][i][3];
        sc[l][i][0] = d_crx[l][i][0];
        sc[l][i][1] = d_crx[l][i][1];
    }

    // Load state directly into registers in config A layout:
    // amp index a = tid | (j<<8) -> perfectly coalesced per j.
    float2 v[16];
    const float* g = sv + (size_t)bidx * DIM;
    #pragma unroll
    for (int j = 0; j < 16; j++) v[j] = make_float2(g[tid + (j << 8)], 0.f);
    __syncthreads();   // params visible

    // ================= Layer 0 =================
    // config A: k0<->bit8(w3) k1<->bit9(w2) k2<->bit10(w1) k3<->bit11(w0)
    gate1q<3>(v, su[0][0]);  gate1q<2>(v, su[0][1]);
    gate1q<1>(v, su[0][2]);  gate1q<0>(v, su[0][3]);
    gatecrx<3, 2>(v, sc[0][0]);   // CRX(w0->w1) = bits (11,10)
    gatecrx<2, 1>(v, sc[0][1]);   // (10,9)
    gatecrx<1, 0>(v, sc[0][2]);   // (9,8)
    remap<0, 1>(v, s, lane, warp);

    // config B: k0<->bit5(w6) k1<->bit6(w5) k2<->bit7(w4) k3<->bit8(w3)
    gate1q<2>(v, su[0][4]);  gate1q<1>(v, su[0][5]);  gate1q<0>(v, su[0][6]);
    gatecrx<3, 2>(v, sc[0][3]);   // (8,7)
    gatecrx<2, 1>(v, sc[0][4]);   // (7,6)
    gatecrx<1, 0>(v, sc[0][5]);   // (6,5)
    remap<1, 2>(v, s, lane, warp);

    // config C: k0<->bit2(w9) k1<->bit3(w8) k2<->bit4(w7) k3<->bit5(w6)
    gate1q<2>(v, su[0][7]);  gate1q<1>(v, su[0][8]);  gate1q<0>(v, su[0][9]);
    gatecrx<3, 2>(v, sc[0][6]);   // (5,4)
    gatecrx<2, 1>(v, sc[0][7]);   // (4,3)
    gatecrx<1, 0>(v, sc[0][8]);   // (3,2)
    remap<2, 3>(v, s, lane, warp);

    // config D: k0<->bit0(w11) k1<->bit1(w10) k2<->bit2(w9) k3<->bit11(w0)
    gate1q<1>(v, su[0][10]); gate1q<0>(v, su[0][11]);
    gatecrx<2, 1>(v, sc[0][9]);   // (2,1)
    gatecrx<1, 0>(v, sc[0][10]);  // (1,0)
    gatecrx<0, 3>(v, sc[0][11]);  // (0,11)

    // ================= Layer 1 (starts in D) =================
    gate1q<3>(v, su[1][0]);  gate1q<2>(v, su[1][9]);
    gate1q<1>(v, su[1][10]); gate1q<0>(v, su[1][11]);
    gatecrx<0, 3>(v, sc[1][11]);  // (0,11)
    gatecrx<1, 0>(v, sc[1][10]);  // (1,0)
    gatecrx<2, 1>(v, sc[1][9]);   // (2,1)
    remap<3, 2>(v, s, lane, warp);

    // config C
    gate1q<3>(v, su[1][6]);  gate1q<2>(v, su[1][7]);  gate1q<1>(v, su[1][8]);
    gatecrx<1, 0>(v, sc[1][8]);   // (3,2)
    gatecrx<2, 1>(v, sc[1][7]);   // (4,3)
    gatecrx<3, 2>(v, sc[1][6]);   // (5,4)
    remap<2, 1>(v, s, lane, warp);

    // config B
    gate1q<3>(v, su[1][3]);  gate1q<2>(v, su[1][4]);  gate1q<1>(v, su[1][5]);
    gatecrx<1, 0>(v, sc[1][5]);   // (6,5)
    gatecrx<2, 1>(v, sc[1][4]);   // (7,6)
    gatecrx<3, 2>(v, sc[1][3]);   // (8,7)
    remap<1, 0>(v, s, lane, warp);

    // config A
    gate1q<2>(v, su[1][1]);  gate1q<1>(v, su[1][2]);
    gatecrx<1, 0>(v, sc[1][2]);   // (9,8)
    gatecrx<2, 1>(v, sc[1][1]);   // (10,9)
    gatecrx<3, 2>(v, sc[1][0]);   // (11,10)

    // ================= Expectation values =================
    // config A: local bits 8..11 -> wires 3,2,1,0
    expv<0>(v, 3, lane, warp, s_red);
    expv<1>(v, 2, lane, warp, s_red);
    expv<2>(v, 1, lane, warp, s_red);
    expv<3>(v, 0, lane, warp, s_red);
    remap<0, 4>(v, s, lane, warp);
    // config E: local bits 4..7 -> wires 7,6,5,4
    expv<0>(v, 7, lane, warp, s_red);
    expv<1>(v, 6, lane, warp, s_red);
    expv<2>(v, 5, lane, warp, s_red);
    expv<3>(v, 4, lane, warp, s_red);
    remap<4, 5>(v, s, lane, warp);
    // config F: local bits 0..3 -> wires 11,10,9,8
    expv<0>(v, 11, lane, warp, s_red);
    expv<1>(v, 10, lane, warp, s_red);
    expv<2>(v, 9,  lane, warp, s_red);
    expv<3>(v, 8,  lane, warp, s_red);
    __syncthreads();

    if (tid < 36) {
        float f = 0.f;
        #pragma unroll
        for (int r = 0; r < 8; r++) f += s_red[tid * 8 + r];
        s_feat[tid] = f;
    }
    __syncthreads();

    if (tid < 10) {
        float acc = bvec[tid];
        #pragma unroll
        for (int j = 0; j < 36; j++) acc += W[tid * 36 + j] * s_feat[j];
        out[(size_t)bidx * 10 + tid] = acc;
    }
}

extern "C" void kernel_launch(void* const* d_in, const int* in_sizes, int n_in,
                              void* d_out, int out_size) {
    const float* sv     = (const float*)d_in[0];   // [2048, 4096]
    const float* angles = (const float*)d_in[1];   // [96]
    const float* W      = (const float*)d_in[2];   // [10, 36]
    const float* b      = (const float*)d_in[3];   // [10]
    float* out = (float*)d_out;                    // [2048, 10]

    prep_gates<<<1, 32>>>(angles);
    sim_kernel<<<2048, NT>>>(sv, W, b, out);
}